// round 15
// baseline (speedup 1.0000x reference)
#include <cuda_runtime.h>
#include <cuda_bf16.h>
#include <math.h>
#include <stdint.h>

#define NROWS  4096
#define EDIM   512
#define QKVLD  1536
#define SPLITS 4

// ---------------- device scratch (no allocations allowed) -------------------
__device__ float g_te[100 * 256];
__device__ int   g_perm[NROWS], g_sortpos[NROWS], g_ssteps[NROWS], g_kstart[64];

__device__ __align__(16) __nv_bfloat16 g_xh   [NROWS * EDIM],  g_xl   [NROWS * EDIM];
__device__ __align__(16) __nv_bfloat16 g_wqkvh[QKVLD * EDIM],  g_wqkvl[QKVLD * EDIM];
__device__ __align__(16) __nv_bfloat16 g_wouth[EDIM * EDIM],   g_woutl[EDIM * EDIM];
__device__ __align__(16) __nv_bfloat16 g_wmlph[EDIM * 896],    g_wmlpl[EDIM * 896];
__device__ __align__(16) __nv_bfloat16 g_qkvh [NROWS * QKVLD], g_qkvl [NROWS * QKVLD];
__device__ __align__(16) __nv_bfloat16 g_vth  [EDIM * NROWS];
__device__ __align__(16) __nv_bfloat16 g_ctxh [NROWS * EDIM],  g_ctxl [NROWS * EDIM];
__device__ __align__(16) __nv_bfloat16 g_combh[NROWS * 896],   g_combl[NROWS * 896];
__device__ float g_h[NROWS * EDIM];
__device__ float g_part[(size_t)SPLITS * NROWS * EDIM];
__device__ float g_psum[SPLITS * 8 * NROWS];

// ---------------- helpers ----------------------------------------------------
__device__ __forceinline__ void mma16816(float* c,
    uint32_t a0, uint32_t a1, uint32_t a2, uint32_t a3,
    uint32_t b0, uint32_t b1) {
    asm volatile(
        "mma.sync.aligned.m16n8k16.row.col.f32.bf16.bf16.f32 "
        "{%0,%1,%2,%3},{%4,%5,%6,%7},{%8,%9},{%0,%1,%2,%3};"
        : "+f"(c[0]), "+f"(c[1]), "+f"(c[2]), "+f"(c[3])
        : "r"(a0), "r"(a1), "r"(a2), "r"(a3), "r"(b0), "r"(b1));
}

__device__ __forceinline__ void ldsm4(uint32_t* r, uint32_t addr) {
    asm volatile("ldmatrix.sync.aligned.m8n8.x4.shared.b16 {%0,%1,%2,%3}, [%4];"
        : "=r"(r[0]), "=r"(r[1]), "=r"(r[2]), "=r"(r[3]) : "r"(addr));
}

__device__ __forceinline__ void cp16(uint32_t dst, const void* src) {
    asm volatile("cp.async.cg.shared.global [%0], [%1], 16;" :: "r"(dst), "l"(src));
}
__device__ __forceinline__ void cp4(uint32_t dst, const void* src) {
    asm volatile("cp.async.ca.shared.global [%0], [%1], 4;" :: "r"(dst), "l"(src));
}
__device__ __forceinline__ void cp_commit() { asm volatile("cp.async.commit_group;"); }
__device__ __forceinline__ void cp_wait0()  { asm volatile("cp.async.wait_group 0;"); }

__device__ __forceinline__ void split2(float v0, float v1, uint32_t& hi, uint32_t& lo) {
    __nv_bfloat162 h = __floats2bfloat162_rn(v0, v1);
    float r0 = v0 - __bfloat162float(h.x);
    float r1 = v1 - __bfloat162float(h.y);
    __nv_bfloat162 l = __floats2bfloat162_rn(r0, r1);
    hi = *reinterpret_cast<uint32_t*>(&h);
    lo = *reinterpret_cast<uint32_t*>(&l);
}

__device__ __forceinline__ uint32_t pack_bf162(float v0, float v1) {
    __nv_bfloat162 h = __floats2bfloat162_rn(v0, v1);
    return *reinterpret_cast<uint32_t*>(&h);
}

// ---------------- time table ---------------------------------------------------
__global__ void build_te_kernel() {
    int t = blockIdx.x * blockDim.x + threadIdx.x;
    if (t >= 100 * 128) return;
    int p = t >> 7;
    int k = t & 127;
    double div = exp(-((double)(2 * k)) * log(10000.0) / 256.0);
    double ang = (double)p * div;
    g_te[p * 256 + 2 * k]     = (float)sin(ang);
    g_te[p * 256 + 2 * k + 1] = (float)cos(ang);
}

// ---------------- deterministic stable sort (parallel chunked) ------------------
__global__ void sort_kernel(const int* __restrict__ steps) {
    __shared__ int s_steps[NROWS];
    __shared__ unsigned short hist[128][100];
    __shared__ int base[100];
    const int t = threadIdx.x;

    for (int i = t; i < NROWS; i += 128) {
        int s = steps[i];
        s_steps[i] = s < 0 ? 0 : (s > 99 ? 99 : s);
    }
    __syncthreads();

    for (int b = 0; b < 100; b++) hist[t][b] = 0;
    const int r0 = t * 32;
    for (int r = 0; r < 32; r++) hist[t][s_steps[r0 + r]]++;
    __syncthreads();

    if (t < 100) {
        int acc = 0;
        for (int c = 0; c < 128; c++) {
            int v = hist[c][t];
            hist[c][t] = (unsigned short)acc;
            acc += v;
        }
        base[t] = acc;
    }
    __syncthreads();
    if (t == 0) {
        int acc = 0;
        for (int b = 0; b < 100; b++) { int v = base[b]; base[b] = acc; acc += v; }
    }
    __syncthreads();

    for (int r = 0; r < 32; r++) {
        int i = r0 + r;
        int s = s_steps[i];
        int pos = base[s] + hist[t][s];
        hist[t][s]++;
        g_perm[pos] = i;
        g_sortpos[i] = pos;
        g_ssteps[pos] = s;
    }
    __syncthreads();

    if (t < 64) {
        int qmin = g_ssteps[t * 64];
        int ks = 0;
        while (ks < 64 && g_ssteps[ks * 64 + 63] < qmin) ks++;
        g_kstart[t] = ks;
    }
}

// ---------------- all fp32 -> bf16 hi/lo splits in ONE kernel -------------------
#define CV0 (NROWS * EDIM)
#define CV1 (CV0 + QKVLD * EDIM)
#define CV2 (CV1 + EDIM * EDIM)
#define CV3 (CV2 + EDIM * 896)
__global__ void cvt_all_kernel(const float* __restrict__ x,
                               const float* __restrict__ wq,
                               const float* __restrict__ wo,
                               const float* __restrict__ wm) {
    int i = (blockIdx.x * blockDim.x + threadIdx.x) * 2;
    if (i >= CV3) return;
    const float* src;
    __nv_bfloat16 *dh, *dl;
    int off;
    if (i < CV0)      { src = x;  dh = g_xh;    dl = g_xl;    off = i; }
    else if (i < CV1) { src = wq; dh = g_wqkvh; dl = g_wqkvl; off = i - CV0; }
    else if (i < CV2) { src = wo; dh = g_wouth; dl = g_woutl; off = i - CV1; }
    else              { src = wm; dh = g_wmlph; dl = g_wmlpl; off = i - CV2; }
    float2 v = *(const float2*)(src + off);
    uint32_t hw, lw;
    split2(v.x, v.y, hw, lw);
    *(uint32_t*)(dh + off) = hw;
    *(uint32_t*)(dl + off) = lw;
}

// ---------------- split-bf16 tensor GEMM, 128x64 tile, K-chunk 32, 3 blk/SM -----
template<int MODE>
__global__ __launch_bounds__(256, 3)
void mma_gemm(const __nv_bfloat16* __restrict__ Ah, const __nv_bfloat16* __restrict__ Al,
              int lda,
              const __nv_bfloat16* __restrict__ Wh, const __nv_bfloat16* __restrict__ Wl,
              const float* __restrict__ bias, int K,
              float* __restrict__ Cf,
              __nv_bfloat16* __restrict__ Ch, __nv_bfloat16* __restrict__ Cl, int ldc) {
    extern __shared__ __align__(16) unsigned char smraw[];
    const uint32_t smb = (uint32_t)__cvta_generic_to_shared(smraw);
    const int t = threadIdx.x;
    const int w = t >> 5, lane = t & 31, g = lane >> 2, tq = lane & 3;
    const int bm = blockIdx.y * 128, bn = blockIdx.x * 64;

    const int arow = t >> 1, ahalf = (t & 1) * 16;
    const uint32_t ldstA = (uint32_t)((arow * 40 + ahalf) * 2);
    const int wrow = t >> 2, wq8 = (t & 3) * 8;
    const uint32_t ldstW = (uint32_t)((wrow * 40 + wq8) * 2);

    const int lr  = lane & 7;
    const int sel = lane >> 3;
    const uint32_t aoff = (uint32_t)(((16 * w + (sel & 1) * 8 + lr) * 40 + (sel >> 1) * 8) * 2);
    const uint32_t boff = (uint32_t)((((sel >> 1) * 8 + lr) * 40 + (sel & 1) * 8) * 2);

    const int nck = K >> 5;

    auto issue = [&](int c, int stg) {
        const size_t ao = (size_t)(bm + arow) * lda + c * 32 + ahalf;
        const size_t wo = (size_t)(bn + wrow) * K   + c * 32 + wq8;
        const uint32_t b0 = smb + (uint32_t)stg * 30720;
        cp16(b0 +         ldstA,      Ah + ao);
        cp16(b0 +         ldstA + 16, Ah + ao + 8);
        cp16(b0 + 10240 + ldstA,      Al + ao);
        cp16(b0 + 10240 + ldstA + 16, Al + ao + 8);
        cp16(b0 + 20480 + ldstW,      Wh + wo);
        cp16(b0 + 25600 + ldstW,      Wl + wo);
        cp_commit();
    };

    float c[8][4];
    #pragma unroll
    for (int i = 0; i < 8; i++)
        #pragma unroll
        for (int j = 0; j < 4; j++) c[i][j] = 0.f;

    issue(0, 0);
    for (int ck = 0; ck < nck; ck++) {
        cp_wait0();
        __syncthreads();
        if (ck + 1 < nck) issue(ck + 1, (ck + 1) & 1);
        const uint32_t b0 = smb + (uint32_t)(ck & 1) * 30720;
        #pragma unroll
        for (int kb = 0; kb < 2; kb++) {
            uint32_t ah[4], al[4];
            ldsm4(ah, b0 +         aoff + kb * 32);
            ldsm4(al, b0 + 10240 + aoff + kb * 32);
            #pragma unroll
            for (int p = 0; p < 4; p++) {
                uint32_t bh[4], bl[4];
                ldsm4(bh, b0 + 20480 + boff + p * 1280 + kb * 32);
                ldsm4(bl, b0 + 25600 + boff + p * 1280 + kb * 32);
                mma16816(c[2 * p],     ah[0], ah[1], ah[2], ah[3], bh[0], bh[1]);
                mma16816(c[2 * p],     ah[0], ah[1], ah[2], ah[3], bl[0], bl[1]);
                mma16816(c[2 * p],     al[0], al[1], al[2], al[3], bh[0], bh[1]);
                mma16816(c[2 * p + 1], ah[0], ah[1], ah[2], ah[3], bh[2], bh[3]);
                mma16816(c[2 * p + 1], ah[0], ah[1], ah[2], ah[3], bl[2], bl[3]);
                mma16816(c[2 * p + 1], al[0], al[1], al[2], al[3], bh[2], bh[3]);
            }
        }
        __syncthreads();
    }

    const int r0 = bm + 16 * w + g, r1 = r0 + 8;
    size_t gr0, gr1;
    if (MODE == 0) { gr0 = g_sortpos[r0]; gr1 = g_sortpos[r1]; }
    else           { gr0 = r0;            gr1 = r1; }
    #pragma unroll
    for (int nb = 0; nb < 8; nb++) {
        const int col = bn + 8 * nb + 2 * tq;
        float b0 = __ldg(bias + col), b1 = __ldg(bias + col + 1);
        float v0 = c[nb][0] + b0, v1 = c[nb][1] + b1;
        float v2 = c[nb][2] + b0, v3 = c[nb][3] + b1;
        if (MODE == 2) {
            *(float2*)&Cf[gr0 * ldc + col] = make_float2(v0, v1);
            *(float2*)&Cf[gr1 * ldc + col] = make_float2(v2, v3);
        } else {
            uint32_t h0, l0, h1, l1;
            split2(v0, v1, h0, l0);
            split2(v2, v3, h1, l1);
            *(uint32_t*)&Ch[gr0 * ldc + col] = h0;
            *(uint32_t*)&Cl[gr0 * ldc + col] = l0;
            *(uint32_t*)&Ch[gr1 * ldc + col] = h1;
            *(uint32_t*)&Cl[gr1 * ldc + col] = l1;
        }
    }
}

// ---------------- V transpose (hi only): sorted v -> [head][d][key] -------------
__global__ __launch_bounds__(128)
void vt_transpose_kernel() {
    __shared__ __align__(16) __nv_bfloat16 th[64 * 72];
    const int t = threadIdx.x;
    const int rb = blockIdx.x * 64, h = blockIdx.y;
    const int lrow = t >> 1, lhalf = (t & 1) * 32;
    const size_t src = (size_t)(rb + lrow) * QKVLD + 1024 + h * 64 + lhalf;
    #pragma unroll
    for (int j = 0; j < 4; j++)
        *(uint4*)&th[lrow * 72 + lhalf + j * 8] = *(const uint4*)(g_qkvh + src + j * 8);
    __syncthreads();
    const int d = t >> 1, kh = (t & 1) * 32;
    __nv_bfloat16* dh = g_vth + (size_t)(h * 64 + d) * NROWS + rb;
    #pragma unroll
    for (int j = 0; j < 16; j++) {
        int sr = kh + 2 * j;
        __nv_bfloat162 a;
        a.x = th[sr * 72 + d]; a.y = th[(sr + 1) * 72 + d];
        *(__nv_bfloat162*)(dh + sr) = a;
    }
}

// ---------------- flash attention: 128-row Q tiles, Q hi-only, 3 blk/SM ---------
// smem bytes: Qh 0 (18432); stage s at 18432+s*27648: Kh, +9216 Kl, +18432 Th;
// sks at 73728 + s*256. Total 74240.  3 blocks/SM: 3*74240 = 222720 <= carveout.
__global__ __launch_bounds__(256, 3)
void attn_kernel() {
    extern __shared__ __align__(16) unsigned char smraw[];
    const uint32_t smb = (uint32_t)__cvta_generic_to_shared(smraw);
    __nv_bfloat16* Qh = (__nv_bfloat16*)smraw;
    int* sks0 = (int*)(smraw + 73728);

    const int qt = blockIdx.x, h = blockIdx.y, sp = blockIdx.z;
    const int qb = qt * 128;
    const int t = threadIdx.x, w = t >> 5, lane = t & 31, g = lane >> 2, tq = lane & 3;
    const int lrow = t >> 1, lhalf = (t & 1) * 32;

    const int lr  = lane & 7;
    const int sel = lane >> 3;
    const uint32_t aoff = (uint32_t)(((16 * w + (sel & 1) * 8 + lr) * 72 + (sel >> 1) * 8) * 2);
    const uint32_t boff = (uint32_t)((((sel >> 1) * 8 + lr) * 72 + (sel & 1) * 8) * 2);

    const int ks0 = g_kstart[2 * qt];
    const int len = (64 - ks0 + SPLITS - 1) / SPLITS;
    const int k0  = ks0 + sp * len;
    const int k1  = (k0 + len < 64) ? (k0 + len) : 64;

    const int krow = t >> 2, koff = (t & 3) * 16;
    const uint32_t kdst = (uint32_t)((krow * 72 + koff) * 2);

    auto issue = [&](int kt, int stg) {
        const int kb64 = kt * 64;
        const size_t ks = (size_t)(kb64 + krow) * QKVLD + 512 + h * 64 + koff;
        const size_t vs = (size_t)(h * 64 + krow) * NROWS + kb64 + koff;
        const uint32_t b0 = smb + 18432 + (uint32_t)stg * 27648;
        cp16(b0 +            kdst,      g_qkvh + ks);
        cp16(b0 +            kdst + 16, g_qkvh + ks + 8);
        cp16(b0 + 1 * 9216 + kdst,      g_qkvl + ks);
        cp16(b0 + 1 * 9216 + kdst + 16, g_qkvl + ks + 8);
        cp16(b0 + 2 * 9216 + kdst,      g_vth  + vs);
        cp16(b0 + 2 * 9216 + kdst + 16, g_vth  + vs + 8);
        if (t < 64) cp4(smb + 73728 + (uint32_t)stg * 256 + t * 4, g_ssteps + kb64 + t);
        cp_commit();
    };

    if (k0 < k1) issue(k0, k0 & 1);
    {
        const size_t src = (size_t)(qb + lrow) * QKVLD + h * 64 + lhalf;
        #pragma unroll
        for (int j = 0; j < 4; j++)
            *(uint4*)&Qh[lrow * 72 + lhalf + j * 8] = *(const uint4*)(g_qkvh + src + j * 8);
    }
    const int sq_a = g_ssteps[qb + 16 * w + g];
    const int sq_b = g_ssteps[qb + 16 * w + g + 8];
    __syncthreads();

    uint32_t qfh[4][4];
    #pragma unroll
    for (int kb = 0; kb < 4; kb++)
        ldsm4(qfh[kb], smb + aoff + kb * 32);

    float o[8][4];
    #pragma unroll
    for (int i = 0; i < 8; i++)
        #pragma unroll
        for (int j = 0; j < 4; j++) o[i][j] = 0.f;
    float ps_a = 0.f, ps_b = 0.f;

    for (int kt = k0; kt < k1; kt++) {
        const int stg = kt & 1;
        cp_wait0();
        __syncthreads();
        if (kt + 1 < k1) issue(kt + 1, (kt + 1) & 1);

        const uint32_t b0 = smb + 18432 + (uint32_t)stg * 27648;
        const int* sksS = sks0 + stg * 64;

        // S = Q_hi (K_hi + K_lo)
        float s[8][4];
        #pragma unroll
        for (int i = 0; i < 8; i++)
            #pragma unroll
            for (int j = 0; j < 4; j++) s[i][j] = 0.f;
        #pragma unroll
        for (int kb = 0; kb < 4; kb++) {
            #pragma unroll
            for (int p = 0; p < 4; p++) {
                uint32_t bh[4], bl[4];
                ldsm4(bh, b0 +        boff + p * 2304 + kb * 32);
                ldsm4(bl, b0 + 9216 + boff + p * 2304 + kb * 32);
                mma16816(s[2 * p],     qfh[kb][0], qfh[kb][1], qfh[kb][2], qfh[kb][3], bh[0], bh[1]);
                mma16816(s[2 * p],     qfh[kb][0], qfh[kb][1], qfh[kb][2], qfh[kb][3], bl[0], bl[1]);
                mma16816(s[2 * p + 1], qfh[kb][0], qfh[kb][1], qfh[kb][2], qfh[kb][3], bh[2], bh[3]);
                mma16816(s[2 * p + 1], qfh[kb][0], qfh[kb][1], qfh[kb][2], qfh[kb][3], bl[2], bl[3]);
            }
        }

        // softmax (fixed shift) + mask; P hi-only frags; exact p in row sums
        uint32_t pah[16];
        #pragma unroll
        for (int nb = 0; nb < 8; nb++) {
            int2 kk = *(const int2*)&sksS[8 * nb + 2 * tq];
            float p0 = __expf(s[nb][0] * 0.125f); if (kk.x < sq_a) p0 = 0.f;
            float p1 = __expf(s[nb][1] * 0.125f); if (kk.y < sq_a) p1 = 0.f;
            float p2 = __expf(s[nb][2] * 0.125f); if (kk.x < sq_b) p2 = 0.f;
            float p3 = __expf(s[nb][3] * 0.125f); if (kk.y < sq_b) p3 = 0.f;
            ps_a += p0 + p1;
            ps_b += p2 + p3;
            pah[2 * nb]     = pack_bf162(p0, p1);
            pah[2 * nb + 1] = pack_bf162(p2, p3);
        }

        // O += P_hi @ V_hi
        #pragma unroll
        for (int kb = 0; kb < 4; kb++) {
            uint32_t a0 = pah[4 * kb],     a1 = pah[4 * kb + 1];
            uint32_t a2 = pah[4 * kb + 2], a3 = pah[4 * kb + 3];
            #pragma unroll
            for (int p = 0; p < 4; p++) {
                uint32_t bh[4];
                ldsm4(bh, b0 + 2 * 9216 + boff + p * 2304 + kb * 32);
                mma16816(o[2 * p],     a0, a1, a2, a3, bh[0], bh[1]);
                mma16816(o[2 * p + 1], a0, a1, a2, a3, bh[2], bh[3]);
            }
        }
        __syncthreads();
    }

    ps_a += __shfl_xor_sync(0xffffffffu, ps_a, 1);
    ps_a += __shfl_xor_sync(0xffffffffu, ps_a, 2);
    ps_b += __shfl_xor_sync(0xffffffffu, ps_b, 1);
    ps_b += __shfl_xor_sync(0xffffffffu, ps_b, 2);
    const int rl0 = 16 * w + g, rl1 = rl0 + 8;
    if (tq == 0) {
        g_psum[(sp * 8 + h) * NROWS + qb + rl0] = ps_a;
        g_psum[(sp * 8 + h) * NROWS + qb + rl1] = ps_b;
    }
    #pragma unroll
    for (int nb = 0; nb < 8; nb++) {
        const int col = h * 64 + 8 * nb + 2 * tq;
        *(float2*)&g_part[((size_t)sp * NROWS + qb + rl0) * EDIM + col] = make_float2(o[nb][0], o[nb][1]);
        *(float2*)&g_part[((size_t)sp * NROWS + qb + rl1) * EDIM + col] = make_float2(o[nb][2], o[nb][3]);
    }
}

// ---------------- fused: combine KV-splits -> ctx AND fill comb 512..895 --------
__global__ void combfill_kernel(const int* __restrict__ dmask,
                                const int* __restrict__ steps,
                                const float* __restrict__ status) {
    const int r = blockIdx.x;
    const int t = threadIdx.x;
    __shared__ float inv[8];
    __shared__ int so;
    if (t == 0) so = g_perm[r];
    if (t >= 312) {
        int hh = t - 312;
        float tot = 0.f;
        #pragma unroll
        for (int s = 0; s < SPLITS; s++) tot += g_psum[(s * 8 + hh) * NROWS + r];
        inv[hh] = 1.f / tot;
    }
    __syncthreads();

    if (t < 128) {
        const int c = t * 4;
        float4 a = *(const float4*)&g_part[(size_t)r * EDIM + c];
        #pragma unroll
        for (int s = 1; s < SPLITS; s++) {
            float4 b = *(const float4*)&g_part[((size_t)s * NROWS + r) * EDIM + c];
            a.x += b.x; a.y += b.y; a.z += b.z; a.w += b.w;
        }
        float iv = inv[c >> 6];
        uint32_t h0, l0, h1, l1;
        split2(a.x * iv, a.y * iv, h0, l0);
        split2(a.z * iv, a.w * iv, h1, l1);
        *(uint32_t*)&g_ctxh[(size_t)r * EDIM + c]     = h0;
        *(uint32_t*)&g_ctxl[(size_t)r * EDIM + c]     = l0;
        *(uint32_t*)&g_ctxh[(size_t)r * EDIM + c + 2] = h1;
        *(uint32_t*)&g_ctxl[(size_t)r * EDIM + c + 2] = l1;
    } else {
        const int col = 2 * (t - 128);
        float v0, v1;
        if (col < 128) {
            int dm = dmask[so];
            v0 = status[dm * 128 + col];
            v1 = status[dm * 128 + col + 1];
        } else {
            int sc = steps[so];
            sc = sc < 0 ? 0 : (sc > 99 ? 99 : sc);
            v0 = g_te[sc * 256 + col - 128];
            v1 = g_te[sc * 256 + col - 127];
        }
        uint32_t hw, lw;
        split2(v0, v1, hw, lw);
        *(uint32_t*)&g_combh[(size_t)r * 896 + 512 + col] = hw;
        *(uint32_t*)&g_combl[(size_t)r * 896 + 512 + col] = lw;
    }
}

// ---------------- LayerNorm -> ReLU -> residual (un-permute) --------------------
__global__ void ln_relu_res_kernel(const float* __restrict__ x,
                                   const float* __restrict__ gamma,
                                   const float* __restrict__ beta,
                                   float* __restrict__ out) {
    const int r = blockIdx.x;
    const int t = threadIdx.x;
    __shared__ float sh[8];
    __shared__ float stat[2];
    __shared__ int so;
    if (t == 0) so = g_perm[r];

    const float* hr = g_h + (size_t)r * EDIM;
    float v0 = hr[t], v1 = hr[t + 256];

    float s = v0 + v1;
    #pragma unroll
    for (int o2 = 16; o2; o2 >>= 1) s += __shfl_xor_sync(0xffffffffu, s, o2);
    if ((t & 31) == 0) sh[t >> 5] = s;
    __syncthreads();
    if (t == 0) {
        float tot = 0.f;
        #pragma unroll
        for (int i = 0; i < 8; i++) tot += sh[i];
        stat[0] = tot * (1.f / 512.f);
    }
    __syncthreads();
    float mu = stat[0];
    float d0 = v0 - mu, d1 = v1 - mu;
    float vv = d0 * d0 + d1 * d1;
    #pragma unroll
    for (int o2 = 16; o2; o2 >>= 1) vv += __shfl_xor_sync(0xffffffffu, vv, o2);
    if ((t & 31) == 0) sh[t >> 5] = vv;
    __syncthreads();
    if (t == 0) {
        float tot = 0.f;
        #pragma unroll
        for (int i = 0; i < 8; i++) tot += sh[i];
        stat[1] = 1.f / sqrtf(tot * (1.f / 512.f) + 1e-5f);
    }
    __syncthreads();
    float inv = stat[1];

    float y0 = fmaxf(d0 * inv * gamma[t]       + beta[t],       0.f);
    float y1 = fmaxf(d1 * inv * gamma[t + 256] + beta[t + 256], 0.f);
    const size_t orow = so;
    out[orow * EDIM + t]       = x[orow * EDIM + t]       + y0;
    out[orow * EDIM + t + 256] = x[orow * EDIM + t + 256] + y1;
}

// ---------------- launch ---------------------------------------------------------
extern "C" void kernel_launch(void* const* d_in, const int* in_sizes, int n_in,
                              void* d_out, int out_size) {
    const float* x      = (const float*)d_in[0];
    const int*   dmask  = (const int*)  d_in[1];
    const int*   steps  = (const int*)  d_in[2];
    const float* status = (const float*)d_in[3];
    const float* wqkv   = (const float*)d_in[4];
    const float* bqkv   = (const float*)d_in[5];
    const float* wout   = (const float*)d_in[6];
    const float* bout   = (const float*)d_in[7];
    const float* wmlp   = (const float*)d_in[8];
    const float* bmlp   = (const float*)d_in[9];
    const float* gamma  = (const float*)d_in[10];
    const float* beta   = (const float*)d_in[11];
    float* out = (float*)d_out;

    __nv_bfloat16 *xh, *xl, *wqh, *wql, *woh, *wol, *wmh, *wml;
    __nv_bfloat16 *qkvh, *qkvl, *ctxh, *ctxl, *combh, *combl;
    float* hbuf;
    cudaGetSymbolAddress((void**)&xh,    g_xh);
    cudaGetSymbolAddress((void**)&xl,    g_xl);
    cudaGetSymbolAddress((void**)&wqh,   g_wqkvh);
    cudaGetSymbolAddress((void**)&wql,   g_wqkvl);
    cudaGetSymbolAddress((void**)&woh,   g_wouth);
    cudaGetSymbolAddress((void**)&wol,   g_woutl);
    cudaGetSymbolAddress((void**)&wmh,   g_wmlph);
    cudaGetSymbolAddress((void**)&wml,   g_wmlpl);
    cudaGetSymbolAddress((void**)&qkvh,  g_qkvh);
    cudaGetSymbolAddress((void**)&qkvl,  g_qkvl);
    cudaGetSymbolAddress((void**)&ctxh,  g_ctxh);
    cudaGetSymbolAddress((void**)&ctxl,  g_ctxl);
    cudaGetSymbolAddress((void**)&combh, g_combh);
    cudaGetSymbolAddress((void**)&combl, g_combl);
    cudaGetSymbolAddress((void**)&hbuf,  g_h);

    const int attn_smem = 74240;
    const int gemm_smem = 61440;
    cudaFuncSetAttribute(attn_kernel, cudaFuncAttributeMaxDynamicSharedMemorySize, attn_smem);
    cudaFuncSetAttribute(attn_kernel, cudaFuncAttributePreferredSharedMemoryCarveout, 100);
    cudaFuncSetAttribute(mma_gemm<0>,  cudaFuncAttributeMaxDynamicSharedMemorySize, gemm_smem);
    cudaFuncSetAttribute(mma_gemm<1>,  cudaFuncAttributeMaxDynamicSharedMemorySize, gemm_smem);
    cudaFuncSetAttribute(mma_gemm<2>,  cudaFuncAttributeMaxDynamicSharedMemorySize, gemm_smem);

    sort_kernel<<<1, 128>>>(steps);
    build_te_kernel<<<50, 256>>>();

    cvt_all_kernel<<<(CV3 / 2 + 255) / 256, 256>>>(x, wqkv, wout, wmlp);

    // qkv = x @ Wqkv^T + b (rows scattered into sorted order)
    mma_gemm<0><<<dim3(24, 32), 256, gemm_smem>>>(xh, xl, EDIM, wqh, wql, bqkv, EDIM,
                                                  nullptr, qkvh, qkvl, QKVLD);

    vt_transpose_kernel<<<dim3(64, 8), 128>>>();

    attn_kernel<<<dim3(32, 8, SPLITS), 256, attn_smem>>>();

    combfill_kernel<<<4096, 320>>>(dmask, steps, status);

    mma_gemm<1><<<dim3(8, 32), 256, gemm_smem>>>(ctxh, ctxl, EDIM, woh, wol, bout, EDIM,
                                                 nullptr, combh, combl, 896);

    mma_gemm<2><<<dim3(8, 32), 256, gemm_smem>>>(combh, combl, 896, wmh, wml, bmlp, 896,
                                                 hbuf, nullptr, nullptr, EDIM);

    ln_relu_res_kernel<<<4096, 256>>>(x, gamma, beta, out);
}

// round 16
// speedup vs baseline: 1.1058x; 1.1058x over previous
#include <cuda_runtime.h>
#include <cuda_bf16.h>
#include <math.h>
#include <stdint.h>

#define NROWS  4096
#define EDIM   512
#define QKVLD  1536
#define SPLITS 4

// ---------------- device scratch (no allocations allowed) -------------------
__device__ float g_te[100 * 256];
__device__ int   g_perm[NROWS], g_sortpos[NROWS], g_ssteps[NROWS], g_kstart[64];

__device__ __align__(16) __nv_bfloat16 g_xh   [NROWS * EDIM],  g_xl   [NROWS * EDIM];
__device__ __align__(16) __nv_bfloat16 g_wqkvh[QKVLD * EDIM],  g_wqkvl[QKVLD * EDIM];
__device__ __align__(16) __nv_bfloat16 g_wouth[EDIM * EDIM],   g_woutl[EDIM * EDIM];
__device__ __align__(16) __nv_bfloat16 g_wmlph[EDIM * 896],    g_wmlpl[EDIM * 896];
__device__ __align__(16) __nv_bfloat16 g_qkvh [NROWS * QKVLD], g_qkvl [NROWS * QKVLD];
__device__ __align__(16) __nv_bfloat16 g_vth  [EDIM * NROWS];
__device__ __align__(16) __nv_bfloat16 g_ctxh [NROWS * EDIM],  g_ctxl [NROWS * EDIM];
__device__ __align__(16) __nv_bfloat16 g_combh[NROWS * 896],   g_combl[NROWS * 896];
__device__ float g_h[NROWS * EDIM];
__device__ float g_part[(size_t)SPLITS * NROWS * EDIM];
__device__ float g_psum[SPLITS * 8 * NROWS];

// ---------------- helpers ----------------------------------------------------
__device__ __forceinline__ void mma16816(float* c,
    uint32_t a0, uint32_t a1, uint32_t a2, uint32_t a3,
    uint32_t b0, uint32_t b1) {
    asm volatile(
        "mma.sync.aligned.m16n8k16.row.col.f32.bf16.bf16.f32 "
        "{%0,%1,%2,%3},{%4,%5,%6,%7},{%8,%9},{%0,%1,%2,%3};"
        : "+f"(c[0]), "+f"(c[1]), "+f"(c[2]), "+f"(c[3])
        : "r"(a0), "r"(a1), "r"(a2), "r"(a3), "r"(b0), "r"(b1));
}

__device__ __forceinline__ void ldsm4(uint32_t* r, uint32_t addr) {
    asm volatile("ldmatrix.sync.aligned.m8n8.x4.shared.b16 {%0,%1,%2,%3}, [%4];"
        : "=r"(r[0]), "=r"(r[1]), "=r"(r[2]), "=r"(r[3]) : "r"(addr));
}

__device__ __forceinline__ void cp16(uint32_t dst, const void* src) {
    asm volatile("cp.async.cg.shared.global [%0], [%1], 16;" :: "r"(dst), "l"(src));
}
__device__ __forceinline__ void cp4(uint32_t dst, const void* src) {
    asm volatile("cp.async.ca.shared.global [%0], [%1], 4;" :: "r"(dst), "l"(src));
}
__device__ __forceinline__ void cp_commit() { asm volatile("cp.async.commit_group;"); }
__device__ __forceinline__ void cp_wait0()  { asm volatile("cp.async.wait_group 0;"); }

__device__ __forceinline__ void split2(float v0, float v1, uint32_t& hi, uint32_t& lo) {
    __nv_bfloat162 h = __floats2bfloat162_rn(v0, v1);
    float r0 = v0 - __bfloat162float(h.x);
    float r1 = v1 - __bfloat162float(h.y);
    __nv_bfloat162 l = __floats2bfloat162_rn(r0, r1);
    hi = *reinterpret_cast<uint32_t*>(&h);
    lo = *reinterpret_cast<uint32_t*>(&l);
}

__device__ __forceinline__ uint32_t pack_bf162(float v0, float v1) {
    __nv_bfloat162 h = __floats2bfloat162_rn(v0, v1);
    return *reinterpret_cast<uint32_t*>(&h);
}

// ---------------- time table ---------------------------------------------------
__global__ void build_te_kernel() {
    int t = blockIdx.x * blockDim.x + threadIdx.x;
    if (t >= 100 * 128) return;
    int p = t >> 7;
    int k = t & 127;
    double div = exp(-((double)(2 * k)) * log(10000.0) / 256.0);
    double ang = (double)p * div;
    g_te[p * 256 + 2 * k]     = (float)sin(ang);
    g_te[p * 256 + 2 * k + 1] = (float)cos(ang);
}

// ---------------- deterministic stable sort (parallel chunked) ------------------
__global__ void sort_kernel(const int* __restrict__ steps) {
    __shared__ int s_steps[NROWS];
    __shared__ unsigned short hist[128][100];
    __shared__ int base[100];
    const int t = threadIdx.x;

    for (int i = t; i < NROWS; i += 128) {
        int s = steps[i];
        s_steps[i] = s < 0 ? 0 : (s > 99 ? 99 : s);
    }
    __syncthreads();

    for (int b = 0; b < 100; b++) hist[t][b] = 0;
    const int r0 = t * 32;
    for (int r = 0; r < 32; r++) hist[t][s_steps[r0 + r]]++;
    __syncthreads();

    if (t < 100) {
        int acc = 0;
        for (int c = 0; c < 128; c++) {
            int v = hist[c][t];
            hist[c][t] = (unsigned short)acc;
            acc += v;
        }
        base[t] = acc;
    }
    __syncthreads();
    if (t == 0) {
        int acc = 0;
        for (int b = 0; b < 100; b++) { int v = base[b]; base[b] = acc; acc += v; }
    }
    __syncthreads();

    for (int r = 0; r < 32; r++) {
        int i = r0 + r;
        int s = s_steps[i];
        int pos = base[s] + hist[t][s];
        hist[t][s]++;
        g_perm[pos] = i;
        g_sortpos[i] = pos;
        g_ssteps[pos] = s;
    }
    __syncthreads();

    if (t < 64) {
        int qmin = g_ssteps[t * 64];
        int ks = 0;
        while (ks < 64 && g_ssteps[ks * 64 + 63] < qmin) ks++;
        g_kstart[t] = ks;
    }
}

// ---------------- all fp32 -> bf16 hi/lo splits in ONE kernel -------------------
#define CV0 (NROWS * EDIM)
#define CV1 (CV0 + QKVLD * EDIM)
#define CV2 (CV1 + EDIM * EDIM)
#define CV3 (CV2 + EDIM * 896)
__global__ void cvt_all_kernel(const float* __restrict__ x,
                               const float* __restrict__ wq,
                               const float* __restrict__ wo,
                               const float* __restrict__ wm) {
    int i = (blockIdx.x * blockDim.x + threadIdx.x) * 2;
    if (i >= CV3) return;
    const float* src;
    __nv_bfloat16 *dh, *dl;
    int off;
    if (i < CV0)      { src = x;  dh = g_xh;    dl = g_xl;    off = i; }
    else if (i < CV1) { src = wq; dh = g_wqkvh; dl = g_wqkvl; off = i - CV0; }
    else if (i < CV2) { src = wo; dh = g_wouth; dl = g_woutl; off = i - CV1; }
    else              { src = wm; dh = g_wmlph; dl = g_wmlpl; off = i - CV2; }
    float2 v = *(const float2*)(src + off);
    uint32_t hw, lw;
    split2(v.x, v.y, hw, lw);
    *(uint32_t*)(dh + off) = hw;
    *(uint32_t*)(dl + off) = lw;
}

// ---------------- split-bf16 tensor GEMM, 128x64 tile, K-chunk 32, 3 blk/SM -----
template<int MODE>
__global__ __launch_bounds__(256, 3)
void mma_gemm(const __nv_bfloat16* __restrict__ Ah, const __nv_bfloat16* __restrict__ Al,
              int lda,
              const __nv_bfloat16* __restrict__ Wh, const __nv_bfloat16* __restrict__ Wl,
              const float* __restrict__ bias, int K,
              float* __restrict__ Cf,
              __nv_bfloat16* __restrict__ Ch, __nv_bfloat16* __restrict__ Cl, int ldc) {
    extern __shared__ __align__(16) unsigned char smraw[];
    const uint32_t smb = (uint32_t)__cvta_generic_to_shared(smraw);
    const int t = threadIdx.x;
    const int w = t >> 5, lane = t & 31, g = lane >> 2, tq = lane & 3;
    const int bm = blockIdx.y * 128, bn = blockIdx.x * 64;

    const int arow = t >> 1, ahalf = (t & 1) * 16;
    const uint32_t ldstA = (uint32_t)((arow * 40 + ahalf) * 2);
    const int wrow = t >> 2, wq8 = (t & 3) * 8;
    const uint32_t ldstW = (uint32_t)((wrow * 40 + wq8) * 2);

    const int lr  = lane & 7;
    const int sel = lane >> 3;
    const uint32_t aoff = (uint32_t)(((16 * w + (sel & 1) * 8 + lr) * 40 + (sel >> 1) * 8) * 2);
    const uint32_t boff = (uint32_t)((((sel >> 1) * 8 + lr) * 40 + (sel & 1) * 8) * 2);

    const int nck = K >> 5;

    auto issue = [&](int c, int stg) {
        const size_t ao = (size_t)(bm + arow) * lda + c * 32 + ahalf;
        const size_t wo = (size_t)(bn + wrow) * K   + c * 32 + wq8;
        const uint32_t b0 = smb + (uint32_t)stg * 30720;
        cp16(b0 +         ldstA,      Ah + ao);
        cp16(b0 +         ldstA + 16, Ah + ao + 8);
        cp16(b0 + 10240 + ldstA,      Al + ao);
        cp16(b0 + 10240 + ldstA + 16, Al + ao + 8);
        cp16(b0 + 20480 + ldstW,      Wh + wo);
        cp16(b0 + 25600 + ldstW,      Wl + wo);
        cp_commit();
    };

    float c[8][4];
    #pragma unroll
    for (int i = 0; i < 8; i++)
        #pragma unroll
        for (int j = 0; j < 4; j++) c[i][j] = 0.f;

    issue(0, 0);
    for (int ck = 0; ck < nck; ck++) {
        cp_wait0();
        __syncthreads();
        if (ck + 1 < nck) issue(ck + 1, (ck + 1) & 1);
        const uint32_t b0 = smb + (uint32_t)(ck & 1) * 30720;
        #pragma unroll
        for (int kb = 0; kb < 2; kb++) {
            uint32_t ah[4], al[4];
            ldsm4(ah, b0 +         aoff + kb * 32);
            ldsm4(al, b0 + 10240 + aoff + kb * 32);
            #pragma unroll
            for (int p = 0; p < 4; p++) {
                uint32_t bh[4], bl[4];
                ldsm4(bh, b0 + 20480 + boff + p * 1280 + kb * 32);
                ldsm4(bl, b0 + 25600 + boff + p * 1280 + kb * 32);
                mma16816(c[2 * p],     ah[0], ah[1], ah[2], ah[3], bh[0], bh[1]);
                mma16816(c[2 * p],     ah[0], ah[1], ah[2], ah[3], bl[0], bl[1]);
                mma16816(c[2 * p],     al[0], al[1], al[2], al[3], bh[0], bh[1]);
                mma16816(c[2 * p + 1], ah[0], ah[1], ah[2], ah[3], bh[2], bh[3]);
                mma16816(c[2 * p + 1], ah[0], ah[1], ah[2], ah[3], bl[2], bl[3]);
                mma16816(c[2 * p + 1], al[0], al[1], al[2], al[3], bh[2], bh[3]);
            }
        }
        __syncthreads();
    }

    const int r0 = bm + 16 * w + g, r1 = r0 + 8;
    size_t gr0, gr1;
    if (MODE == 0) { gr0 = g_sortpos[r0]; gr1 = g_sortpos[r1]; }
    else           { gr0 = r0;            gr1 = r1; }
    #pragma unroll
    for (int nb = 0; nb < 8; nb++) {
        const int col = bn + 8 * nb + 2 * tq;
        float b0 = __ldg(bias + col), b1 = __ldg(bias + col + 1);
        float v0 = c[nb][0] + b0, v1 = c[nb][1] + b1;
        float v2 = c[nb][2] + b0, v3 = c[nb][3] + b1;
        if (MODE == 2) {
            *(float2*)&Cf[gr0 * ldc + col] = make_float2(v0, v1);
            *(float2*)&Cf[gr1 * ldc + col] = make_float2(v2, v3);
        } else {
            uint32_t h0, l0, h1, l1;
            split2(v0, v1, h0, l0);
            split2(v2, v3, h1, l1);
            *(uint32_t*)&Ch[gr0 * ldc + col] = h0;
            *(uint32_t*)&Cl[gr0 * ldc + col] = l0;
            *(uint32_t*)&Ch[gr1 * ldc + col] = h1;
            *(uint32_t*)&Cl[gr1 * ldc + col] = l1;
        }
    }
}

// ---------------- V transpose (hi only): sorted v -> [head][d][key] -------------
__global__ __launch_bounds__(128)
void vt_transpose_kernel() {
    __shared__ __align__(16) __nv_bfloat16 th[64 * 72];
    const int t = threadIdx.x;
    const int rb = blockIdx.x * 64, h = blockIdx.y;
    const int lrow = t >> 1, lhalf = (t & 1) * 32;
    const size_t src = (size_t)(rb + lrow) * QKVLD + 1024 + h * 64 + lhalf;
    #pragma unroll
    for (int j = 0; j < 4; j++)
        *(uint4*)&th[lrow * 72 + lhalf + j * 8] = *(const uint4*)(g_qkvh + src + j * 8);
    __syncthreads();
    const int d = t >> 1, kh = (t & 1) * 32;
    __nv_bfloat16* dh = g_vth + (size_t)(h * 64 + d) * NROWS + rb;
    #pragma unroll
    for (int j = 0; j < 16; j++) {
        int sr = kh + 2 * j;
        __nv_bfloat162 a;
        a.x = th[sr * 72 + d]; a.y = th[(sr + 1) * 72 + d];
        *(__nv_bfloat162*)(dh + sr) = a;
    }
}

// ---------------- flash attention: 128-row Q tiles, all-hi bf16, cp.async -------
// smem bytes: Qh 0 (18432); stage s at 18432 + s*18432: Kh (9216), Th (9216);
// sks at 55296 + s*256. Total 55808.
__global__ __launch_bounds__(256, 2)
void attn_kernel() {
    extern __shared__ __align__(16) unsigned char smraw[];
    const uint32_t smb = (uint32_t)__cvta_generic_to_shared(smraw);
    __nv_bfloat16* Qh = (__nv_bfloat16*)smraw;
    int* sks0 = (int*)(smraw + 55296);

    const int qt = blockIdx.x, h = blockIdx.y, sp = blockIdx.z;
    const int qb = qt * 128;
    const int t = threadIdx.x, w = t >> 5, lane = t & 31, g = lane >> 2, tq = lane & 3;
    const int lrow = t >> 1, lhalf = (t & 1) * 32;

    const int lr  = lane & 7;
    const int sel = lane >> 3;
    const uint32_t aoff = (uint32_t)(((16 * w + (sel & 1) * 8 + lr) * 72 + (sel >> 1) * 8) * 2);
    const uint32_t boff = (uint32_t)((((sel >> 1) * 8 + lr) * 72 + (sel & 1) * 8) * 2);

    const int ks0 = g_kstart[2 * qt];
    const int len = (64 - ks0 + SPLITS - 1) / SPLITS;
    const int k0  = ks0 + sp * len;
    const int k1  = (k0 + len < 64) ? (k0 + len) : 64;

    const int krow = t >> 2, koff = (t & 3) * 16;
    const uint32_t kdst = (uint32_t)((krow * 72 + koff) * 2);

    auto issue = [&](int kt, int stg) {
        const int kb64 = kt * 64;
        const size_t ks = (size_t)(kb64 + krow) * QKVLD + 512 + h * 64 + koff;
        const size_t vs = (size_t)(h * 64 + krow) * NROWS + kb64 + koff;
        const uint32_t b0 = smb + 18432 + (uint32_t)stg * 18432;
        cp16(b0 +        kdst,      g_qkvh + ks);
        cp16(b0 +        kdst + 16, g_qkvh + ks + 8);
        cp16(b0 + 9216 + kdst,      g_vth  + vs);
        cp16(b0 + 9216 + kdst + 16, g_vth  + vs + 8);
        if (t < 64) cp4(smb + 55296 + (uint32_t)stg * 256 + t * 4, g_ssteps + kb64 + t);
        cp_commit();
    };

    if (k0 < k1) issue(k0, k0 & 1);
    {
        const size_t src = (size_t)(qb + lrow) * QKVLD + h * 64 + lhalf;
        #pragma unroll
        for (int j = 0; j < 4; j++)
            *(uint4*)&Qh[lrow * 72 + lhalf + j * 8] = *(const uint4*)(g_qkvh + src + j * 8);
    }
    const int sq_a = g_ssteps[qb + 16 * w + g];
    const int sq_b = g_ssteps[qb + 16 * w + g + 8];
    __syncthreads();

    uint32_t qfh[4][4];
    #pragma unroll
    for (int kb = 0; kb < 4; kb++)
        ldsm4(qfh[kb], smb + aoff + kb * 32);

    float o[8][4];
    #pragma unroll
    for (int i = 0; i < 8; i++)
        #pragma unroll
        for (int j = 0; j < 4; j++) o[i][j] = 0.f;
    float ps_a = 0.f, ps_b = 0.f;

    for (int kt = k0; kt < k1; kt++) {
        const int stg = kt & 1;
        cp_wait0();
        __syncthreads();
        if (kt + 1 < k1) issue(kt + 1, (kt + 1) & 1);

        const uint32_t b0 = smb + 18432 + (uint32_t)stg * 18432;
        const int* sksS = sks0 + stg * 64;

        // S = Q_hi K_hi  (pure bf16 product; logit noise ~1e-5 end-to-end measured)
        float s[8][4];
        #pragma unroll
        for (int i = 0; i < 8; i++)
            #pragma unroll
            for (int j = 0; j < 4; j++) s[i][j] = 0.f;
        #pragma unroll
        for (int kb = 0; kb < 4; kb++) {
            #pragma unroll
            for (int p = 0; p < 4; p++) {
                uint32_t bh[4];
                ldsm4(bh, b0 + boff + p * 2304 + kb * 32);
                mma16816(s[2 * p],     qfh[kb][0], qfh[kb][1], qfh[kb][2], qfh[kb][3], bh[0], bh[1]);
                mma16816(s[2 * p + 1], qfh[kb][0], qfh[kb][1], qfh[kb][2], qfh[kb][3], bh[2], bh[3]);
            }
        }

        // softmax (fixed shift) + mask; P hi-only frags; exact p in row sums
        uint32_t pah[16];
        #pragma unroll
        for (int nb = 0; nb < 8; nb++) {
            int2 kk = *(const int2*)&sksS[8 * nb + 2 * tq];
            float p0 = __expf(s[nb][0] * 0.125f); if (kk.x < sq_a) p0 = 0.f;
            float p1 = __expf(s[nb][1] * 0.125f); if (kk.y < sq_a) p1 = 0.f;
            float p2 = __expf(s[nb][2] * 0.125f); if (kk.x < sq_b) p2 = 0.f;
            float p3 = __expf(s[nb][3] * 0.125f); if (kk.y < sq_b) p3 = 0.f;
            ps_a += p0 + p1;
            ps_b += p2 + p3;
            pah[2 * nb]     = pack_bf162(p0, p1);
            pah[2 * nb + 1] = pack_bf162(p2, p3);
        }

        // O += P_hi @ V_hi
        #pragma unroll
        for (int kb = 0; kb < 4; kb++) {
            uint32_t a0 = pah[4 * kb],     a1 = pah[4 * kb + 1];
            uint32_t a2 = pah[4 * kb + 2], a3 = pah[4 * kb + 3];
            #pragma unroll
            for (int p = 0; p < 4; p++) {
                uint32_t bh[4];
                ldsm4(bh, b0 + 9216 + boff + p * 2304 + kb * 32);
                mma16816(o[2 * p],     a0, a1, a2, a3, bh[0], bh[1]);
                mma16816(o[2 * p + 1], a0, a1, a2, a3, bh[2], bh[3]);
            }
        }
        __syncthreads();
    }

    ps_a += __shfl_xor_sync(0xffffffffu, ps_a, 1);
    ps_a += __shfl_xor_sync(0xffffffffu, ps_a, 2);
    ps_b += __shfl_xor_sync(0xffffffffu, ps_b, 1);
    ps_b += __shfl_xor_sync(0xffffffffu, ps_b, 2);
    const int rl0 = 16 * w + g, rl1 = rl0 + 8;
    if (tq == 0) {
        g_psum[(sp * 8 + h) * NROWS + qb + rl0] = ps_a;
        g_psum[(sp * 8 + h) * NROWS + qb + rl1] = ps_b;
    }
    #pragma unroll
    for (int nb = 0; nb < 8; nb++) {
        const int col = h * 64 + 8 * nb + 2 * tq;
        *(float2*)&g_part[((size_t)sp * NROWS + qb + rl0) * EDIM + col] = make_float2(o[nb][0], o[nb][1]);
        *(float2*)&g_part[((size_t)sp * NROWS + qb + rl1) * EDIM + col] = make_float2(o[nb][2], o[nb][3]);
    }
}

// ---------------- fused: combine KV-splits -> ctx AND fill comb 512..895 --------
__global__ void combfill_kernel(const int* __restrict__ dmask,
                                const int* __restrict__ steps,
                                const float* __restrict__ status) {
    const int r = blockIdx.x;
    const int t = threadIdx.x;
    __shared__ float inv[8];
    __shared__ int so;
    if (t == 0) so = g_perm[r];
    if (t >= 312) {
        int hh = t - 312;
        float tot = 0.f;
        #pragma unroll
        for (int s = 0; s < SPLITS; s++) tot += g_psum[(s * 8 + hh) * NROWS + r];
        inv[hh] = 1.f / tot;
    }
    __syncthreads();

    if (t < 128) {
        const int c = t * 4;
        float4 a = *(const float4*)&g_part[(size_t)r * EDIM + c];
        #pragma unroll
        for (int s = 1; s < SPLITS; s++) {
            float4 b = *(const float4*)&g_part[((size_t)s * NROWS + r) * EDIM + c];
            a.x += b.x; a.y += b.y; a.z += b.z; a.w += b.w;
        }
        float iv = inv[c >> 6];
        uint32_t h0, l0, h1, l1;
        split2(a.x * iv, a.y * iv, h0, l0);
        split2(a.z * iv, a.w * iv, h1, l1);
        *(uint32_t*)&g_ctxh[(size_t)r * EDIM + c]     = h0;
        *(uint32_t*)&g_ctxl[(size_t)r * EDIM + c]     = l0;
        *(uint32_t*)&g_ctxh[(size_t)r * EDIM + c + 2] = h1;
        *(uint32_t*)&g_ctxl[(size_t)r * EDIM + c + 2] = l1;
    } else {
        const int col = 2 * (t - 128);
        float v0, v1;
        if (col < 128) {
            int dm = dmask[so];
            v0 = status[dm * 128 + col];
            v1 = status[dm * 128 + col + 1];
        } else {
            int sc = steps[so];
            sc = sc < 0 ? 0 : (sc > 99 ? 99 : sc);
            v0 = g_te[sc * 256 + col - 128];
            v1 = g_te[sc * 256 + col - 127];
        }
        uint32_t hw, lw;
        split2(v0, v1, hw, lw);
        *(uint32_t*)&g_combh[(size_t)r * 896 + 512 + col] = hw;
        *(uint32_t*)&g_combl[(size_t)r * 896 + 512 + col] = lw;
    }
}

// ---------------- LayerNorm -> ReLU -> residual (un-permute) --------------------
__global__ void ln_relu_res_kernel(const float* __restrict__ x,
                                   const float* __restrict__ gamma,
                                   const float* __restrict__ beta,
                                   float* __restrict__ out) {
    const int r = blockIdx.x;
    const int t = threadIdx.x;
    __shared__ float sh[8];
    __shared__ float stat[2];
    __shared__ int so;
    if (t == 0) so = g_perm[r];

    const float* hr = g_h + (size_t)r * EDIM;
    float v0 = hr[t], v1 = hr[t + 256];

    float s = v0 + v1;
    #pragma unroll
    for (int o2 = 16; o2; o2 >>= 1) s += __shfl_xor_sync(0xffffffffu, s, o2);
    if ((t & 31) == 0) sh[t >> 5] = s;
    __syncthreads();
    if (t == 0) {
        float tot = 0.f;
        #pragma unroll
        for (int i = 0; i < 8; i++) tot += sh[i];
        stat[0] = tot * (1.f / 512.f);
    }
    __syncthreads();
    float mu = stat[0];
    float d0 = v0 - mu, d1 = v1 - mu;
    float vv = d0 * d0 + d1 * d1;
    #pragma unroll
    for (int o2 = 16; o2; o2 >>= 1) vv += __shfl_xor_sync(0xffffffffu, vv, o2);
    if ((t & 31) == 0) sh[t >> 5] = vv;
    __syncthreads();
    if (t == 0) {
        float tot = 0.f;
        #pragma unroll
        for (int i = 0; i < 8; i++) tot += sh[i];
        stat[1] = 1.f / sqrtf(tot * (1.f / 512.f) + 1e-5f);
    }
    __syncthreads();
    float inv = stat[1];

    float y0 = fmaxf(d0 * inv * gamma[t]       + beta[t],       0.f);
    float y1 = fmaxf(d1 * inv * gamma[t + 256] + beta[t + 256], 0.f);
    const size_t orow = so;
    out[orow * EDIM + t]       = x[orow * EDIM + t]       + y0;
    out[orow * EDIM + t + 256] = x[orow * EDIM + t + 256] + y1;
}

// ---------------- launch ---------------------------------------------------------
extern "C" void kernel_launch(void* const* d_in, const int* in_sizes, int n_in,
                              void* d_out, int out_size) {
    const float* x      = (const float*)d_in[0];
    const int*   dmask  = (const int*)  d_in[1];
    const int*   steps  = (const int*)  d_in[2];
    const float* status = (const float*)d_in[3];
    const float* wqkv   = (const float*)d_in[4];
    const float* bqkv   = (const float*)d_in[5];
    const float* wout   = (const float*)d_in[6];
    const float* bout   = (const float*)d_in[7];
    const float* wmlp   = (const float*)d_in[8];
    const float* bmlp   = (const float*)d_in[9];
    const float* gamma  = (const float*)d_in[10];
    const float* beta   = (const float*)d_in[11];
    float* out = (float*)d_out;

    __nv_bfloat16 *xh, *xl, *wqh, *wql, *woh, *wol, *wmh, *wml;
    __nv_bfloat16 *qkvh, *qkvl, *ctxh, *ctxl, *combh, *combl;
    float* hbuf;
    cudaGetSymbolAddress((void**)&xh,    g_xh);
    cudaGetSymbolAddress((void**)&xl,    g_xl);
    cudaGetSymbolAddress((void**)&wqh,   g_wqkvh);
    cudaGetSymbolAddress((void**)&wql,   g_wqkvl);
    cudaGetSymbolAddress((void**)&woh,   g_wouth);
    cudaGetSymbolAddress((void**)&wol,   g_woutl);
    cudaGetSymbolAddress((void**)&wmh,   g_wmlph);
    cudaGetSymbolAddress((void**)&wml,   g_wmlpl);
    cudaGetSymbolAddress((void**)&qkvh,  g_qkvh);
    cudaGetSymbolAddress((void**)&qkvl,  g_qkvl);
    cudaGetSymbolAddress((void**)&ctxh,  g_ctxh);
    cudaGetSymbolAddress((void**)&ctxl,  g_ctxl);
    cudaGetSymbolAddress((void**)&combh, g_combh);
    cudaGetSymbolAddress((void**)&combl, g_combl);
    cudaGetSymbolAddress((void**)&hbuf,  g_h);

    const int attn_smem = 55808;
    const int gemm_smem = 61440;
    cudaFuncSetAttribute(attn_kernel, cudaFuncAttributeMaxDynamicSharedMemorySize, attn_smem);
    cudaFuncSetAttribute(mma_gemm<0>,  cudaFuncAttributeMaxDynamicSharedMemorySize, gemm_smem);
    cudaFuncSetAttribute(mma_gemm<1>,  cudaFuncAttributeMaxDynamicSharedMemorySize, gemm_smem);
    cudaFuncSetAttribute(mma_gemm<2>,  cudaFuncAttributeMaxDynamicSharedMemorySize, gemm_smem);

    sort_kernel<<<1, 128>>>(steps);
    build_te_kernel<<<50, 256>>>();

    cvt_all_kernel<<<(CV3 / 2 + 255) / 256, 256>>>(x, wqkv, wout, wmlp);

    // qkv = x @ Wqkv^T + b (rows scattered into sorted order)
    mma_gemm<0><<<dim3(24, 32), 256, gemm_smem>>>(xh, xl, EDIM, wqh, wql, bqkv, EDIM,
                                                  nullptr, qkvh, qkvl, QKVLD);

    vt_transpose_kernel<<<dim3(64, 8), 128>>>();

    attn_kernel<<<dim3(32, 8, SPLITS), 256, attn_smem>>>();

    combfill_kernel<<<4096, 320>>>(dmask, steps, status);

    mma_gemm<1><<<dim3(8, 32), 256, gemm_smem>>>(ctxh, ctxl, EDIM, woh, wol, bout, EDIM,
                                                 nullptr, combh, combl, 896);

    mma_gemm<2><<<dim3(8, 32), 256, gemm_smem>>>(combh, combl, 896, wmh, wml, bmlp, 896,
                                                 hbuf, nullptr, nullptr, EDIM);

    ln_relu_res_kernel<<<4096, 256>>>(x, gamma, beta, out);
}

// round 17
// speedup vs baseline: 1.2383x; 1.1199x over previous
#include <cuda_runtime.h>
#include <cuda_bf16.h>
#include <math.h>
#include <stdint.h>

#define NROWS  4096
#define EDIM   512
#define QKVLD  1536
#define SPLITS 4

// ---------------- device scratch (no allocations allowed) -------------------
__device__ float g_te[100 * 256];
__device__ int   g_perm[NROWS], g_sortpos[NROWS], g_ssteps[NROWS], g_kstart[64];

__device__ __align__(16) __nv_bfloat16 g_xh   [NROWS * EDIM],  g_xl   [NROWS * EDIM];
__device__ __align__(16) __nv_bfloat16 g_wqkvh[QKVLD * EDIM],  g_wqkvl[QKVLD * EDIM];
__device__ __align__(16) __nv_bfloat16 g_wouth[EDIM * EDIM],   g_woutl[EDIM * EDIM];
__device__ __align__(16) __nv_bfloat16 g_wmlph[EDIM * 896],    g_wmlpl[EDIM * 896];
__device__ __align__(16) __nv_bfloat16 g_qkvh [NROWS * QKVLD];
__device__ __align__(16) __nv_bfloat16 g_vth  [EDIM * NROWS];
__device__ __align__(16) __nv_bfloat16 g_ctxh [NROWS * EDIM],  g_ctxl [NROWS * EDIM];
__device__ __align__(16) __nv_bfloat16 g_combh[NROWS * 896],   g_combl[NROWS * 896];
__device__ float g_h[NROWS * EDIM];
__device__ float g_part[(size_t)SPLITS * NROWS * EDIM];
__device__ float g_psum[SPLITS * 8 * NROWS];

// ---------------- helpers ----------------------------------------------------
__device__ __forceinline__ void mma16816(float* c,
    uint32_t a0, uint32_t a1, uint32_t a2, uint32_t a3,
    uint32_t b0, uint32_t b1) {
    asm volatile(
        "mma.sync.aligned.m16n8k16.row.col.f32.bf16.bf16.f32 "
        "{%0,%1,%2,%3},{%4,%5,%6,%7},{%8,%9},{%0,%1,%2,%3};"
        : "+f"(c[0]), "+f"(c[1]), "+f"(c[2]), "+f"(c[3])
        : "r"(a0), "r"(a1), "r"(a2), "r"(a3), "r"(b0), "r"(b1));
}

__device__ __forceinline__ void ldsm4(uint32_t* r, uint32_t addr) {
    asm volatile("ldmatrix.sync.aligned.m8n8.x4.shared.b16 {%0,%1,%2,%3}, [%4];"
        : "=r"(r[0]), "=r"(r[1]), "=r"(r[2]), "=r"(r[3]) : "r"(addr));
}

__device__ __forceinline__ void cp16(uint32_t dst, const void* src) {
    asm volatile("cp.async.cg.shared.global [%0], [%1], 16;" :: "r"(dst), "l"(src));
}
__device__ __forceinline__ void cp4(uint32_t dst, const void* src) {
    asm volatile("cp.async.ca.shared.global [%0], [%1], 4;" :: "r"(dst), "l"(src));
}
__device__ __forceinline__ void cp_commit() { asm volatile("cp.async.commit_group;"); }
__device__ __forceinline__ void cp_wait0()  { asm volatile("cp.async.wait_group 0;"); }

__device__ __forceinline__ void split2(float v0, float v1, uint32_t& hi, uint32_t& lo) {
    __nv_bfloat162 h = __floats2bfloat162_rn(v0, v1);
    float r0 = v0 - __bfloat162float(h.x);
    float r1 = v1 - __bfloat162float(h.y);
    __nv_bfloat162 l = __floats2bfloat162_rn(r0, r1);
    hi = *reinterpret_cast<uint32_t*>(&h);
    lo = *reinterpret_cast<uint32_t*>(&l);
}

__device__ __forceinline__ uint32_t pack_bf162(float v0, float v1) {
    __nv_bfloat162 h = __floats2bfloat162_rn(v0, v1);
    return *reinterpret_cast<uint32_t*>(&h);
}

// ---------------- time table ---------------------------------------------------
__global__ void build_te_kernel() {
    int t = blockIdx.x * blockDim.x + threadIdx.x;
    if (t >= 100 * 128) return;
    int p = t >> 7;
    int k = t & 127;
    double div = exp(-((double)(2 * k)) * log(10000.0) / 256.0);
    double ang = (double)p * div;
    g_te[p * 256 + 2 * k]     = (float)sin(ang);
    g_te[p * 256 + 2 * k + 1] = (float)cos(ang);
}

// ---------------- deterministic stable sort (parallel chunked) ------------------
__global__ void sort_kernel(const int* __restrict__ steps) {
    __shared__ int s_steps[NROWS];
    __shared__ unsigned short hist[128][100];
    __shared__ int base[100];
    const int t = threadIdx.x;

    for (int i = t; i < NROWS; i += 128) {
        int s = steps[i];
        s_steps[i] = s < 0 ? 0 : (s > 99 ? 99 : s);
    }
    __syncthreads();

    for (int b = 0; b < 100; b++) hist[t][b] = 0;
    const int r0 = t * 32;
    for (int r = 0; r < 32; r++) hist[t][s_steps[r0 + r]]++;
    __syncthreads();

    if (t < 100) {
        int acc = 0;
        for (int c = 0; c < 128; c++) {
            int v = hist[c][t];
            hist[c][t] = (unsigned short)acc;
            acc += v;
        }
        base[t] = acc;
    }
    __syncthreads();
    if (t == 0) {
        int acc = 0;
        for (int b = 0; b < 100; b++) { int v = base[b]; base[b] = acc; acc += v; }
    }
    __syncthreads();

    for (int r = 0; r < 32; r++) {
        int i = r0 + r;
        int s = s_steps[i];
        int pos = base[s] + hist[t][s];
        hist[t][s]++;
        g_perm[pos] = i;
        g_sortpos[i] = pos;
        g_ssteps[pos] = s;
    }
    __syncthreads();

    if (t < 64) {
        int qmin = g_ssteps[t * 64];
        int ks = 0;
        while (ks < 64 && g_ssteps[ks * 64 + 63] < qmin) ks++;
        g_kstart[t] = ks;
    }
}

// ---------------- all fp32 -> bf16 hi/lo splits in ONE kernel -------------------
#define CV0 (NROWS * EDIM)
#define CV1 (CV0 + QKVLD * EDIM)
#define CV2 (CV1 + EDIM * EDIM)
#define CV3 (CV2 + EDIM * 896)
__global__ void cvt_all_kernel(const float* __restrict__ x,
                               const float* __restrict__ wq,
                               const float* __restrict__ wo,
                               const float* __restrict__ wm) {
    int i = (blockIdx.x * blockDim.x + threadIdx.x) * 2;
    if (i >= CV3) return;
    const float* src;
    __nv_bfloat16 *dh, *dl;
    int off;
    if (i < CV0)      { src = x;  dh = g_xh;    dl = g_xl;    off = i; }
    else if (i < CV1) { src = wq; dh = g_wqkvh; dl = g_wqkvl; off = i - CV0; }
    else if (i < CV2) { src = wo; dh = g_wouth; dl = g_woutl; off = i - CV1; }
    else              { src = wm; dh = g_wmlph; dl = g_wmlpl; off = i - CV2; }
    float2 v = *(const float2*)(src + off);
    uint32_t hw, lw;
    split2(v.x, v.y, hw, lw);
    *(uint32_t*)(dh + off) = hw;
    *(uint32_t*)(dl + off) = lw;
}

// ---------------- split-bf16 tensor GEMM, 128x64 tile, K-chunk 32, 3 blk/SM -----
// MODE 0: 2-term (A_hi only; output hi-only, scattered) — feeds bf16-hi consumers
// MODE 1: 3-term, bf16 hi/lo out, direct rows
// MODE 2: 3-term, fp32 out, direct rows
template<int MODE>
__global__ __launch_bounds__(256, 3)
void mma_gemm(const __nv_bfloat16* __restrict__ Ah, const __nv_bfloat16* __restrict__ Al,
              int lda,
              const __nv_bfloat16* __restrict__ Wh, const __nv_bfloat16* __restrict__ Wl,
              const float* __restrict__ bias, int K,
              float* __restrict__ Cf,
              __nv_bfloat16* __restrict__ Ch, __nv_bfloat16* __restrict__ Cl, int ldc) {
    extern __shared__ __align__(16) unsigned char smraw[];
    const uint32_t smb = (uint32_t)__cvta_generic_to_shared(smraw);
    const int t = threadIdx.x;
    const int w = t >> 5, lane = t & 31, g = lane >> 2, tq = lane & 3;
    const int bm = blockIdx.y * 128, bn = blockIdx.x * 64;

    const int arow = t >> 1, ahalf = (t & 1) * 16;
    const uint32_t ldstA = (uint32_t)((arow * 40 + ahalf) * 2);
    const int wrow = t >> 2, wq8 = (t & 3) * 8;
    const uint32_t ldstW = (uint32_t)((wrow * 40 + wq8) * 2);

    const int lr  = lane & 7;
    const int sel = lane >> 3;
    const uint32_t aoff = (uint32_t)(((16 * w + (sel & 1) * 8 + lr) * 40 + (sel >> 1) * 8) * 2);
    const uint32_t boff = (uint32_t)((((sel >> 1) * 8 + lr) * 40 + (sel & 1) * 8) * 2);

    const int nck = K >> 5;

    auto issue = [&](int c, int stg) {
        const size_t ao = (size_t)(bm + arow) * lda + c * 32 + ahalf;
        const size_t wo = (size_t)(bn + wrow) * K   + c * 32 + wq8;
        const uint32_t b0 = smb + (uint32_t)stg * 30720;
        cp16(b0 +         ldstA,      Ah + ao);
        cp16(b0 +         ldstA + 16, Ah + ao + 8);
        if (MODE != 0) {
            cp16(b0 + 10240 + ldstA,      Al + ao);
            cp16(b0 + 10240 + ldstA + 16, Al + ao + 8);
        }
        cp16(b0 + 20480 + ldstW,      Wh + wo);
        cp16(b0 + 25600 + ldstW,      Wl + wo);
        cp_commit();
    };

    float c[8][4];
    #pragma unroll
    for (int i = 0; i < 8; i++)
        #pragma unroll
        for (int j = 0; j < 4; j++) c[i][j] = 0.f;

    issue(0, 0);
    for (int ck = 0; ck < nck; ck++) {
        cp_wait0();
        __syncthreads();
        if (ck + 1 < nck) issue(ck + 1, (ck + 1) & 1);
        const uint32_t b0 = smb + (uint32_t)(ck & 1) * 30720;
        #pragma unroll
        for (int kb = 0; kb < 2; kb++) {
            uint32_t ah[4], al[4];
            ldsm4(ah, b0 + aoff + kb * 32);
            if (MODE != 0) ldsm4(al, b0 + 10240 + aoff + kb * 32);
            #pragma unroll
            for (int p = 0; p < 4; p++) {
                uint32_t bh[4], bl[4];
                ldsm4(bh, b0 + 20480 + boff + p * 1280 + kb * 32);
                ldsm4(bl, b0 + 25600 + boff + p * 1280 + kb * 32);
                mma16816(c[2 * p],     ah[0], ah[1], ah[2], ah[3], bh[0], bh[1]);
                mma16816(c[2 * p],     ah[0], ah[1], ah[2], ah[3], bl[0], bl[1]);
                if (MODE != 0)
                    mma16816(c[2 * p], al[0], al[1], al[2], al[3], bh[0], bh[1]);
                mma16816(c[2 * p + 1], ah[0], ah[1], ah[2], ah[3], bh[2], bh[3]);
                mma16816(c[2 * p + 1], ah[0], ah[1], ah[2], ah[3], bl[2], bl[3]);
                if (MODE != 0)
                    mma16816(c[2 * p + 1], al[0], al[1], al[2], al[3], bh[2], bh[3]);
            }
        }
        __syncthreads();
    }

    const int r0 = bm + 16 * w + g, r1 = r0 + 8;
    size_t gr0, gr1;
    if (MODE == 0) { gr0 = g_sortpos[r0]; gr1 = g_sortpos[r1]; }
    else           { gr0 = r0;            gr1 = r1; }
    #pragma unroll
    for (int nb = 0; nb < 8; nb++) {
        const int col = bn + 8 * nb + 2 * tq;
        float b0 = __ldg(bias + col), b1 = __ldg(bias + col + 1);
        float v0 = c[nb][0] + b0, v1 = c[nb][1] + b1;
        float v2 = c[nb][2] + b0, v3 = c[nb][3] + b1;
        if (MODE == 2) {
            *(float2*)&Cf[gr0 * ldc + col] = make_float2(v0, v1);
            *(float2*)&Cf[gr1 * ldc + col] = make_float2(v2, v3);
        } else if (MODE == 0) {
            *(uint32_t*)&Ch[gr0 * ldc + col] = pack_bf162(v0, v1);
            *(uint32_t*)&Ch[gr1 * ldc + col] = pack_bf162(v2, v3);
        } else {
            uint32_t h0, l0, h1, l1;
            split2(v0, v1, h0, l0);
            split2(v2, v3, h1, l1);
            *(uint32_t*)&Ch[gr0 * ldc + col] = h0;
            *(uint32_t*)&Cl[gr0 * ldc + col] = l0;
            *(uint32_t*)&Ch[gr1 * ldc + col] = h1;
            *(uint32_t*)&Cl[gr1 * ldc + col] = l1;
        }
    }
}

// ---------------- V transpose (hi only): sorted v -> [head][d][key] -------------
__global__ __launch_bounds__(128)
void vt_transpose_kernel() {
    __shared__ __align__(16) __nv_bfloat16 th[64 * 72];
    const int t = threadIdx.x;
    const int rb = blockIdx.x * 64, h = blockIdx.y;
    const int lrow = t >> 1, lhalf = (t & 1) * 32;
    const size_t src = (size_t)(rb + lrow) * QKVLD + 1024 + h * 64 + lhalf;
    #pragma unroll
    for (int j = 0; j < 4; j++)
        *(uint4*)&th[lrow * 72 + lhalf + j * 8] = *(const uint4*)(g_qkvh + src + j * 8);
    __syncthreads();
    const int d = t >> 1, kh = (t & 1) * 32;
    __nv_bfloat16* dh = g_vth + (size_t)(h * 64 + d) * NROWS + rb;
    #pragma unroll
    for (int j = 0; j < 16; j++) {
        int sr = kh + 2 * j;
        __nv_bfloat162 a;
        a.x = th[sr * 72 + d]; a.y = th[(sr + 1) * 72 + d];
        *(__nv_bfloat162*)(dh + sr) = a;
    }
}

// ---------------- flash attention: 128-row Q tiles, all-hi bf16, cp.async -------
// smem bytes: Qh 0 (18432); stage s at 18432 + s*18432: Kh (9216), Th (9216);
// sks at 55296 + s*256. Total 55808.
__global__ __launch_bounds__(256, 2)
void attn_kernel() {
    extern __shared__ __align__(16) unsigned char smraw[];
    const uint32_t smb = (uint32_t)__cvta_generic_to_shared(smraw);
    __nv_bfloat16* Qh = (__nv_bfloat16*)smraw;
    int* sks0 = (int*)(smraw + 55296);

    const int qt = blockIdx.x, h = blockIdx.y, sp = blockIdx.z;
    const int qb = qt * 128;
    const int t = threadIdx.x, w = t >> 5, lane = t & 31, g = lane >> 2, tq = lane & 3;
    const int lrow = t >> 1, lhalf = (t & 1) * 32;

    const int lr  = lane & 7;
    const int sel = lane >> 3;
    const uint32_t aoff = (uint32_t)(((16 * w + (sel & 1) * 8 + lr) * 72 + (sel >> 1) * 8) * 2);
    const uint32_t boff = (uint32_t)((((sel >> 1) * 8 + lr) * 72 + (sel & 1) * 8) * 2);

    const int ks0 = g_kstart[2 * qt];
    const int len = (64 - ks0 + SPLITS - 1) / SPLITS;
    const int k0  = ks0 + sp * len;
    const int k1  = (k0 + len < 64) ? (k0 + len) : 64;

    const int krow = t >> 2, koff = (t & 3) * 16;
    const uint32_t kdst = (uint32_t)((krow * 72 + koff) * 2);

    auto issue = [&](int kt, int stg) {
        const int kb64 = kt * 64;
        const size_t ks = (size_t)(kb64 + krow) * QKVLD + 512 + h * 64 + koff;
        const size_t vs = (size_t)(h * 64 + krow) * NROWS + kb64 + koff;
        const uint32_t b0 = smb + 18432 + (uint32_t)stg * 18432;
        cp16(b0 +        kdst,      g_qkvh + ks);
        cp16(b0 +        kdst + 16, g_qkvh + ks + 8);
        cp16(b0 + 9216 + kdst,      g_vth  + vs);
        cp16(b0 + 9216 + kdst + 16, g_vth  + vs + 8);
        if (t < 64) cp4(smb + 55296 + (uint32_t)stg * 256 + t * 4, g_ssteps + kb64 + t);
        cp_commit();
    };

    if (k0 < k1) issue(k0, k0 & 1);
    {
        const size_t src = (size_t)(qb + lrow) * QKVLD + h * 64 + lhalf;
        #pragma unroll
        for (int j = 0; j < 4; j++)
            *(uint4*)&Qh[lrow * 72 + lhalf + j * 8] = *(const uint4*)(g_qkvh + src + j * 8);
    }
    const int sq_a = g_ssteps[qb + 16 * w + g];
    const int sq_b = g_ssteps[qb + 16 * w + g + 8];
    __syncthreads();

    uint32_t qfh[4][4];
    #pragma unroll
    for (int kb = 0; kb < 4; kb++)
        ldsm4(qfh[kb], smb + aoff + kb * 32);

    float o[8][4];
    #pragma unroll
    for (int i = 0; i < 8; i++)
        #pragma unroll
        for (int j = 0; j < 4; j++) o[i][j] = 0.f;
    float ps_a = 0.f, ps_b = 0.f;

    for (int kt = k0; kt < k1; kt++) {
        const int stg = kt & 1;
        cp_wait0();
        __syncthreads();
        if (kt + 1 < k1) issue(kt + 1, (kt + 1) & 1);

        const uint32_t b0 = smb + 18432 + (uint32_t)stg * 18432;
        const int* sksS = sks0 + stg * 64;

        // S = Q_hi K_hi
        float s[8][4];
        #pragma unroll
        for (int i = 0; i < 8; i++)
            #pragma unroll
            for (int j = 0; j < 4; j++) s[i][j] = 0.f;
        #pragma unroll
        for (int kb = 0; kb < 4; kb++) {
            #pragma unroll
            for (int p = 0; p < 4; p++) {
                uint32_t bh[4];
                ldsm4(bh, b0 + boff + p * 2304 + kb * 32);
                mma16816(s[2 * p],     qfh[kb][0], qfh[kb][1], qfh[kb][2], qfh[kb][3], bh[0], bh[1]);
                mma16816(s[2 * p + 1], qfh[kb][0], qfh[kb][1], qfh[kb][2], qfh[kb][3], bh[2], bh[3]);
            }
        }

        // softmax (fixed shift) + mask; P hi-only frags; exact p in row sums
        uint32_t pah[16];
        #pragma unroll
        for (int nb = 0; nb < 8; nb++) {
            int2 kk = *(const int2*)&sksS[8 * nb + 2 * tq];
            float p0 = __expf(s[nb][0] * 0.125f); if (kk.x < sq_a) p0 = 0.f;
            float p1 = __expf(s[nb][1] * 0.125f); if (kk.y < sq_a) p1 = 0.f;
            float p2 = __expf(s[nb][2] * 0.125f); if (kk.x < sq_b) p2 = 0.f;
            float p3 = __expf(s[nb][3] * 0.125f); if (kk.y < sq_b) p3 = 0.f;
            ps_a += p0 + p1;
            ps_b += p2 + p3;
            pah[2 * nb]     = pack_bf162(p0, p1);
            pah[2 * nb + 1] = pack_bf162(p2, p3);
        }

        // O += P_hi @ V_hi
        #pragma unroll
        for (int kb = 0; kb < 4; kb++) {
            uint32_t a0 = pah[4 * kb],     a1 = pah[4 * kb + 1];
            uint32_t a2 = pah[4 * kb + 2], a3 = pah[4 * kb + 3];
            #pragma unroll
            for (int p = 0; p < 4; p++) {
                uint32_t bh[4];
                ldsm4(bh, b0 + 9216 + boff + p * 2304 + kb * 32);
                mma16816(o[2 * p],     a0, a1, a2, a3, bh[0], bh[1]);
                mma16816(o[2 * p + 1], a0, a1, a2, a3, bh[2], bh[3]);
            }
        }
        __syncthreads();
    }

    ps_a += __shfl_xor_sync(0xffffffffu, ps_a, 1);
    ps_a += __shfl_xor_sync(0xffffffffu, ps_a, 2);
    ps_b += __shfl_xor_sync(0xffffffffu, ps_b, 1);
    ps_b += __shfl_xor_sync(0xffffffffu, ps_b, 2);
    const int rl0 = 16 * w + g, rl1 = rl0 + 8;
    if (tq == 0) {
        g_psum[(sp * 8 + h) * NROWS + qb + rl0] = ps_a;
        g_psum[(sp * 8 + h) * NROWS + qb + rl1] = ps_b;
    }
    #pragma unroll
    for (int nb = 0; nb < 8; nb++) {
        const int col = h * 64 + 8 * nb + 2 * tq;
        *(float2*)&g_part[((size_t)sp * NROWS + qb + rl0) * EDIM + col] = make_float2(o[nb][0], o[nb][1]);
        *(float2*)&g_part[((size_t)sp * NROWS + qb + rl1) * EDIM + col] = make_float2(o[nb][2], o[nb][3]);
    }
}

// ---------------- fused: combine KV-splits -> ctx AND fill comb 512..895 --------
__global__ void combfill_kernel(const int* __restrict__ dmask,
                                const int* __restrict__ steps,
                                const float* __restrict__ status) {
    const int r = blockIdx.x;
    const int t = threadIdx.x;
    __shared__ float inv[8];
    __shared__ int so;
    if (t == 0) so = g_perm[r];
    if (t >= 312) {
        int hh = t - 312;
        float tot = 0.f;
        #pragma unroll
        for (int s = 0; s < SPLITS; s++) tot += g_psum[(s * 8 + hh) * NROWS + r];
        inv[hh] = 1.f / tot;
    }
    __syncthreads();

    if (t < 128) {
        const int c = t * 4;
        float4 a = *(const float4*)&g_part[(size_t)r * EDIM + c];
        #pragma unroll
        for (int s = 1; s < SPLITS; s++) {
            float4 b = *(const float4*)&g_part[((size_t)s * NROWS + r) * EDIM + c];
            a.x += b.x; a.y += b.y; a.z += b.z; a.w += b.w;
        }
        float iv = inv[c >> 6];
        uint32_t h0, l0, h1, l1;
        split2(a.x * iv, a.y * iv, h0, l0);
        split2(a.z * iv, a.w * iv, h1, l1);
        *(uint32_t*)&g_ctxh[(size_t)r * EDIM + c]     = h0;
        *(uint32_t*)&g_ctxl[(size_t)r * EDIM + c]     = l0;
        *(uint32_t*)&g_ctxh[(size_t)r * EDIM + c + 2] = h1;
        *(uint32_t*)&g_ctxl[(size_t)r * EDIM + c + 2] = l1;
    } else {
        const int col = 2 * (t - 128);
        float v0, v1;
        if (col < 128) {
            int dm = dmask[so];
            v0 = status[dm * 128 + col];
            v1 = status[dm * 128 + col + 1];
        } else {
            int sc = steps[so];
            sc = sc < 0 ? 0 : (sc > 99 ? 99 : sc);
            v0 = g_te[sc * 256 + col - 128];
            v1 = g_te[sc * 256 + col - 127];
        }
        uint32_t hw, lw;
        split2(v0, v1, hw, lw);
        *(uint32_t*)&g_combh[(size_t)r * 896 + 512 + col] = hw;
        *(uint32_t*)&g_combl[(size_t)r * 896 + 512 + col] = lw;
    }
}

// ---------------- LayerNorm -> ReLU -> residual (un-permute) --------------------
__global__ void ln_relu_res_kernel(const float* __restrict__ x,
                                   const float* __restrict__ gamma,
                                   const float* __restrict__ beta,
                                   float* __restrict__ out) {
    const int r = blockIdx.x;
    const int t = threadIdx.x;
    __shared__ float sh[8];
    __shared__ float stat[2];
    __shared__ int so;
    if (t == 0) so = g_perm[r];

    const float* hr = g_h + (size_t)r * EDIM;
    float v0 = hr[t], v1 = hr[t + 256];

    float s = v0 + v1;
    #pragma unroll
    for (int o2 = 16; o2; o2 >>= 1) s += __shfl_xor_sync(0xffffffffu, s, o2);
    if ((t & 31) == 0) sh[t >> 5] = s;
    __syncthreads();
    if (t == 0) {
        float tot = 0.f;
        #pragma unroll
        for (int i = 0; i < 8; i++) tot += sh[i];
        stat[0] = tot * (1.f / 512.f);
    }
    __syncthreads();
    float mu = stat[0];
    float d0 = v0 - mu, d1 = v1 - mu;
    float vv = d0 * d0 + d1 * d1;
    #pragma unroll
    for (int o2 = 16; o2; o2 >>= 1) vv += __shfl_xor_sync(0xffffffffu, vv, o2);
    if ((t & 31) == 0) sh[t >> 5] = vv;
    __syncthreads();
    if (t == 0) {
        float tot = 0.f;
        #pragma unroll
        for (int i = 0; i < 8; i++) tot += sh[i];
        stat[1] = 1.f / sqrtf(tot * (1.f / 512.f) + 1e-5f);
    }
    __syncthreads();
    float inv = stat[1];

    float y0 = fmaxf(d0 * inv * gamma[t]       + beta[t],       0.f);
    float y1 = fmaxf(d1 * inv * gamma[t + 256] + beta[t + 256], 0.f);
    const size_t orow = so;
    out[orow * EDIM + t]       = x[orow * EDIM + t]       + y0;
    out[orow * EDIM + t + 256] = x[orow * EDIM + t + 256] + y1;
}

// ---------------- launch ---------------------------------------------------------
extern "C" void kernel_launch(void* const* d_in, const int* in_sizes, int n_in,
                              void* d_out, int out_size) {
    const float* x      = (const float*)d_in[0];
    const int*   dmask  = (const int*)  d_in[1];
    const int*   steps  = (const int*)  d_in[2];
    const float* status = (const float*)d_in[3];
    const float* wqkv   = (const float*)d_in[4];
    const float* bqkv   = (const float*)d_in[5];
    const float* wout   = (const float*)d_in[6];
    const float* bout   = (const float*)d_in[7];
    const float* wmlp   = (const float*)d_in[8];
    const float* bmlp   = (const float*)d_in[9];
    const float* gamma  = (const float*)d_in[10];
    const float* beta   = (const float*)d_in[11];
    float* out = (float*)d_out;

    __nv_bfloat16 *xh, *xl, *wqh, *wql, *woh, *wol, *wmh, *wml;
    __nv_bfloat16 *qkvh, *ctxh, *ctxl, *combh, *combl;
    float* hbuf;
    cudaGetSymbolAddress((void**)&xh,    g_xh);
    cudaGetSymbolAddress((void**)&xl,    g_xl);
    cudaGetSymbolAddress((void**)&wqh,   g_wqkvh);
    cudaGetSymbolAddress((void**)&wql,   g_wqkvl);
    cudaGetSymbolAddress((void**)&woh,   g_wouth);
    cudaGetSymbolAddress((void**)&wol,   g_woutl);
    cudaGetSymbolAddress((void**)&wmh,   g_wmlph);
    cudaGetSymbolAddress((void**)&wml,   g_wmlpl);
    cudaGetSymbolAddress((void**)&qkvh,  g_qkvh);
    cudaGetSymbolAddress((void**)&ctxh,  g_ctxh);
    cudaGetSymbolAddress((void**)&ctxl,  g_ctxl);
    cudaGetSymbolAddress((void**)&combh, g_combh);
    cudaGetSymbolAddress((void**)&combl, g_combl);
    cudaGetSymbolAddress((void**)&hbuf,  g_h);

    const int attn_smem = 55808;
    const int gemm_smem = 61440;
    cudaFuncSetAttribute(attn_kernel, cudaFuncAttributeMaxDynamicSharedMemorySize, attn_smem);
    cudaFuncSetAttribute(mma_gemm<0>,  cudaFuncAttributeMaxDynamicSharedMemorySize, gemm_smem);
    cudaFuncSetAttribute(mma_gemm<1>,  cudaFuncAttributeMaxDynamicSharedMemorySize, gemm_smem);
    cudaFuncSetAttribute(mma_gemm<2>,  cudaFuncAttributeMaxDynamicSharedMemorySize, gemm_smem);

    sort_kernel<<<1, 128>>>(steps);
    build_te_kernel<<<50, 256>>>();

    cvt_all_kernel<<<(CV3 / 2 + 255) / 256, 256>>>(x, wqkv, wout, wmlp);

    // qkv = x @ Wqkv^T + b (2-term; hi-only output, scattered to sorted order)
    mma_gemm<0><<<dim3(24, 32), 256, gemm_smem>>>(xh, xl, EDIM, wqh, wql, bqkv, EDIM,
                                                  nullptr, qkvh, nullptr, QKVLD);

    vt_transpose_kernel<<<dim3(64, 8), 128>>>();

    attn_kernel<<<dim3(32, 8, SPLITS), 256, attn_smem>>>();

    combfill_kernel<<<4096, 320>>>(dmask, steps, status);

    mma_gemm<1><<<dim3(8, 32), 256, gemm_smem>>>(ctxh, ctxl, EDIM, woh, wol, bout, EDIM,
                                                 nullptr, combh, combl, 896);

    mma_gemm<2><<<dim3(8, 32), 256, gemm_smem>>>(combh, combl, 896, wmh, wml, bmlp, 896,
                                                 hbuf, nullptr, nullptr, EDIM);

    ln_relu_res_kernel<<<4096, 256>>>(x, gamma, beta, out);
}